// round 17
// baseline (speedup 1.0000x reference)
#include <cuda_runtime.h>
#include <cuda_fp16.h>
#include <cstdint>

#define BB 2
#define SS 2048
#define DD 512
#define HH 8
#define LR 7
#define MTOT (BB*SS)        // 4096
#define NBLK (SS/16)        // 128 i-blocks per batch

// scratch
__device__ __half g_qh[MTOT * DD];       // q projection, fp16
__device__ __half g_kh[MTOT * DD];       // k projection, fp16
__device__ __half g_ah[MTOT * DD];       // hs fp16
__device__ __half g_b2q[DD * DD];        // Wq^T fp16, rows = n
__device__ __half g_b2k[DD * DD];        // Wk^T fp16, rows = n

#define SWZ128(off) ((off) ^ (((off) >> 3) & 0x70))

__device__ __forceinline__ uint32_t smem_u32(const void* p) {
    uint32_t a;
    asm("{ .reg .u64 t; cvta.to.shared.u64 t, %1; cvt.u32.u64 %0, t; }" : "=r"(a) : "l"(p));
    return a;
}
__device__ __forceinline__ void cp16(uint32_t s, const void* g) {
    asm volatile("cp.async.cg.shared.global [%0], [%1], 16;" :: "r"(s), "l"(g));
}
#define CP_COMMIT() asm volatile("cp.async.commit_group;" ::: "memory")

__device__ __forceinline__ void ldm_x4(uint32_t& r0, uint32_t& r1, uint32_t& r2, uint32_t& r3, uint32_t a) {
    asm volatile("ldmatrix.sync.aligned.m8n8.x4.shared.b16 {%0,%1,%2,%3}, [%4];"
                 : "=r"(r0), "=r"(r1), "=r"(r2), "=r"(r3) : "r"(a));
}
__device__ __forceinline__ void ldm_x2(uint32_t& r0, uint32_t& r1, uint32_t a) {
    asm volatile("ldmatrix.sync.aligned.m8n8.x2.shared.b16 {%0,%1}, [%2];"
                 : "=r"(r0), "=r"(r1) : "r"(a));
}
__device__ __forceinline__ void ldm_x2t(uint32_t& r0, uint32_t& r1, uint32_t a) {
    asm volatile("ldmatrix.sync.aligned.m8n8.x2.trans.shared.b16 {%0,%1}, [%2];"
                 : "=r"(r0), "=r"(r1) : "r"(a));
}
__device__ __forceinline__ void mma16816(float* d, const uint32_t* a, const uint32_t* b) {
    asm volatile("mma.sync.aligned.m16n8k16.row.col.f32.f16.f16.f32 "
                 "{%0,%1,%2,%3}, {%4,%5,%6,%7}, {%8,%9}, {%0,%1,%2,%3};"
                 : "+f"(d[0]), "+f"(d[1]), "+f"(d[2]), "+f"(d[3])
                 : "r"(a[0]), "r"(a[1]), "r"(a[2]), "r"(a[3]), "r"(b[0]), "r"(b[1]));
}
__device__ __forceinline__ uint32_t packh2(float x, float y) {
    __half2 h = __floats2half2_rn(x, y);
    return *reinterpret_cast<uint32_t*>(&h);
}

// ---------------------------------------------------------------------------
// split hidden_states to fp16
// ---------------------------------------------------------------------------
__global__ void split_hs(const float* __restrict__ hs) {
    int idx = blockIdx.x * 256 + threadIdx.x;
    float4 v = ((const float4*)hs)[idx];
    __half2 h0 = __floats2half2_rn(v.x, v.y);
    __half2 h1 = __floats2half2_rn(v.z, v.w);
    __half2* p = (__half2*)(g_ah + 4 * (size_t)idx);
    p[0] = h0; p[1] = h1;
}

// ---------------------------------------------------------------------------
// split + transpose W (stored [k, n]) into fp16 [n, 512]
// ---------------------------------------------------------------------------
__global__ void split_w(const float* __restrict__ Wq, const float* __restrict__ Wk) {
    __shared__ float t[32][33];
    const float* W = blockIdx.z ? Wk : Wq;
    __half* B2 = blockIdx.z ? g_b2k : g_b2q;
    int n0 = blockIdx.x * 32, k0 = blockIdx.y * 32;
    int tx = threadIdx.x, ty = threadIdx.y;
#pragma unroll
    for (int r = 0; r < 4; r++)
        t[ty + r * 8][tx] = W[(size_t)(k0 + ty + r * 8) * DD + n0 + tx];
    __syncthreads();
#pragma unroll
    for (int r = 0; r < 4; r++) {
        int n = n0 + ty + r * 8, k = k0 + tx;
        B2[(size_t)n * DD + k] = __float2half(t[tx][ty + r * 8]);
    }
}

// ---------------------------------------------------------------------------
// mma.sync fp16 GEMM: q and k projections, K=512, fp16 out (unchanged)
// ---------------------------------------------------------------------------
#define MT 128
#define NT 128
#define NKT 8
#define STG 32768u
#define NSTG 3
#define GEMM_SMEM (NSTG * STG)

__device__ __forceinline__ void load_tile(int tile, int stg,
                                          const char* Ab, const char* Bb,
                                          uint32_t sb, int tid) {
    size_t koff = (size_t)tile * 128;
    uint32_t sA = sb + (uint32_t)stg * STG;
    uint32_t sB = sA + 16384u;
#pragma unroll
    for (int c = 0; c < 4; c++) {
        int q = tid + c * 256;
        int r = q >> 3, col = (q & 7) * 16;
        cp16(sA + SWZ128(r * 128 + col), Ab + (size_t)r * 1024 + koff + col);
    }
#pragma unroll
    for (int c = 0; c < 4; c++) {
        int q = tid + c * 256;
        int r = q >> 3, col = (q & 7) * 16;
        cp16(sB + SWZ128(r * 128 + col), Bb + (size_t)r * 1024 + koff + col);
    }
}

__global__ __launch_bounds__(256, 2)
void gemm2() {
    extern __shared__ char smem[];
    uint32_t sb = smem_u32(smem);
    const int tid = threadIdx.x, wid = tid >> 5, lane = tid & 31;
    const int m0 = blockIdx.x * MT;
    const int n0 = blockIdx.y * NT;

    const __half* B2 = blockIdx.z ? g_b2k : g_b2q;
    __half* C       = blockIdx.z ? g_kh : g_qh;

    const char* Ab = (const char*)g_ah + (size_t)m0 * 1024;
    const char* Bb = (const char*)B2 + (size_t)n0 * 1024;

    const int wm = wid & 1;
    const int wn = wid >> 1;

    float acc[4][4][4];
#pragma unroll
    for (int i = 0; i < 4; i++)
#pragma unroll
        for (int j = 0; j < 4; j++)
#pragma unroll
            for (int r = 0; r < 4; r++) acc[i][j][r] = 0.f;

    load_tile(0, 0, Ab, Bb, sb, tid); CP_COMMIT();
    load_tile(1, 1, Ab, Bb, sb, tid); CP_COMMIT();

    const int a_row = wm * 64 + (lane & 15);
    const int a_cg  = (lane >> 4) * 16;
    const int b_row = wn * 32 + (lane & 7);
    const int b_cg  = ((lane >> 3) & 1) * 16;

    for (int t = 0; t < NKT; t++) {
        asm volatile("cp.async.wait_group 1;" ::: "memory");
        __syncthreads();

        if (t + 2 < NKT)
            load_tile(t + 2, (t + 2) % NSTG, Ab, Bb, sb, tid);
        CP_COMMIT();

        uint32_t sA = sb + (uint32_t)(t % NSTG) * STG;
        uint32_t sB = sA + 16384u;
#pragma unroll
        for (int ks = 0; ks < 4; ks++) {
            uint32_t af[4][4], bf[4][2];
#pragma unroll
            for (int mi = 0; mi < 4; mi++)
                ldm_x4(af[mi][0], af[mi][1], af[mi][2], af[mi][3],
                       sA + SWZ128((a_row + mi * 16) * 128 + ks * 32 + a_cg));
#pragma unroll
            for (int ni = 0; ni < 4; ni++)
                ldm_x2(bf[ni][0], bf[ni][1],
                       sB + SWZ128((b_row + ni * 8) * 128 + ks * 32 + b_cg));
#pragma unroll
            for (int mi = 0; mi < 4; mi++)
#pragma unroll
                for (int ni = 0; ni < 4; ni++)
                    mma16816(acc[mi][ni], af[mi], bf[ni]);
        }
    }

    const int er = lane >> 2;
    const int ec = (lane & 3) * 2;
#pragma unroll
    for (int mi = 0; mi < 4; mi++) {
        int r0 = m0 + wm * 64 + mi * 16 + er;
#pragma unroll
        for (int ni = 0; ni < 4; ni++) {
            int cc = n0 + wn * 32 + ni * 8 + ec;
            __half2 v01 = __floats2half2_rn(acc[mi][ni][0], acc[mi][ni][1]);
            __half2 v23 = __floats2half2_rn(acc[mi][ni][2], acc[mi][ni][3]);
            *(__half2*)(C + (size_t)r0 * DD + cc) = v01;
            *(__half2*)(C + (size_t)(r0 + 8) * DD + cc) = v23;
        }
    }
}

// ---------------------------------------------------------------------------
// ctxf v4: tensor-core fused block, d-split for 2x grid parallelism.
// CTA = (16-i block, d-half). warp = head. q fragments via direct LDG.
//  scores S[16x32] = Q_h x Kw_h^T (MMA) -> mask -> register softmax
//  weights repacked in regs as A fragment; ctx MMA over 256 d columns.
// smem: kw 32KB + hs-half 16KB = 48KB -> 3 CTAs/SM. grid (256, 2) = 512 CTAs.
// ---------------------------------------------------------------------------
#define CTXF_SMEM (32768 + 16384)   // 49152

__global__ __launch_bounds__(256, 3)
void ctxf(float* __restrict__ out) {
    extern __shared__ char smemraw[];
    uint32_t Kb = smem_u32(smemraw);      // kw: 32 rows x 1KB
    uint32_t Bb = Kb + 32768;             // hs: 32 rows x 512B (d-half)

    const int blk = blockIdx.x >> 1, dhalf = blockIdx.x & 1, b = blockIdx.y;
    const int i0 = blk * 16;
    const int tid = threadIdx.x, wid = tid >> 5, lane = tid & 31;

    // group 0: kw rows (full 512 cols)
    {
        const char* kg = (const char*)g_kh + (size_t)b * SS * 1024;
        for (int idx = tid; idx < 32 * 64; idx += 256) {
            int r = idx >> 6, u = idx & 63;
            int j = i0 - LR + r;
            j = j < 0 ? 0 : (j >= SS ? SS - 1 : j);
            cp16(Kb + r * 1024 + ((u ^ (r & 7)) << 4), kg + (size_t)j * 1024 + u * 16);
        }
        CP_COMMIT();
    }
    // group 1: hs window, this CTA's 256-col half
    {
        const char* ah = (const char*)g_ah + (size_t)b * SS * 1024 + dhalf * 512;
        for (int idx = tid; idx < 32 * 32; idx += 256) {
            int r = idx >> 5, u = idx & 31;
            int j = i0 - LR + r;
            j = j < 0 ? 0 : (j >= SS ? SS - 1 : j);
            cp16(Bb + r * 512 + ((u ^ (r & 7)) << 4), ah + (size_t)j * 1024 + u * 16);
        }
        CP_COMMIT();
    }

    const int h = wid;
    const int er = lane >> 2, ec = (lane & 3) * 2;

    // q fragments direct from global (fragment-layout LDG, L2-hot)
    uint32_t qa[4][4];
    {
        const __half* qg = g_qh + ((size_t)b * SS + i0) * DD + h * 64;
#pragma unroll
        for (int ks = 0; ks < 4; ks++) {
            const __half* p0 = qg + (size_t)er * DD + ks * 16 + ec;
            const __half* p1 = qg + (size_t)(er + 8) * DD + ks * 16 + ec;
            qa[ks][0] = *(const uint32_t*)(p0);
            qa[ks][1] = *(const uint32_t*)(p1);
            qa[ks][2] = *(const uint32_t*)(p0 + 8);
            qa[ks][3] = *(const uint32_t*)(p1 + 8);
        }
    }

    asm volatile("cp.async.wait_group 1;" ::: "memory");   // kw ready
    __syncthreads();

    // ---- scores S[16 i][32 jw] via MMA ----
    float s[4][4];
#pragma unroll
    for (int ni = 0; ni < 4; ni++)
#pragma unroll
        for (int r = 0; r < 4; r++) s[ni][r] = 0.f;

#pragma unroll
    for (int ks = 0; ks < 4; ks++) {
#pragma unroll
        for (int ni = 0; ni < 4; ni++) {
            uint32_t bf[2];
            int r = ni * 8 + (lane & 7);
            int u = h * 8 + ks * 2 + ((lane >> 3) & 1);
            ldm_x2(bf[0], bf[1], Kb + r * 1024 + ((u ^ (r & 7)) << 4));
            mma16816(s[ni], qa[ks], bf);
        }
    }

    // ---- mask + scale ----
#pragma unroll
    for (int ni = 0; ni < 4; ni++)
#pragma unroll
        for (int e = 0; e < 4; e++) {
            int row = (e < 2) ? er : er + 8;
            int col = ni * 8 + ec + (e & 1);
            int j = i0 - LR + col;
            bool valid = (col >= row) && (col <= row + 14) && (j >= 0) && (j < SS);
            s[ni][e] = valid ? s[ni][e] * 0.125f : -1e30f;
        }

    // ---- row softmax (rows er, er+8 across the 4-lane quad) ----
    float m0 = -1e30f, m1 = -1e30f;
#pragma unroll
    for (int ni = 0; ni < 4; ni++) {
        m0 = fmaxf(m0, fmaxf(s[ni][0], s[ni][1]));
        m1 = fmaxf(m1, fmaxf(s[ni][2], s[ni][3]));
    }
    m0 = fmaxf(m0, __shfl_xor_sync(0xffffffffu, m0, 1));
    m0 = fmaxf(m0, __shfl_xor_sync(0xffffffffu, m0, 2));
    m1 = fmaxf(m1, __shfl_xor_sync(0xffffffffu, m1, 1));
    m1 = fmaxf(m1, __shfl_xor_sync(0xffffffffu, m1, 2));

    float s0 = 0.f, s1 = 0.f;
#pragma unroll
    for (int ni = 0; ni < 4; ni++) {
        s[ni][0] = __expf(s[ni][0] - m0); s0 += s[ni][0];
        s[ni][1] = __expf(s[ni][1] - m0); s0 += s[ni][1];
        s[ni][2] = __expf(s[ni][2] - m1); s1 += s[ni][2];
        s[ni][3] = __expf(s[ni][3] - m1); s1 += s[ni][3];
    }
    s0 += __shfl_xor_sync(0xffffffffu, s0, 1);
    s0 += __shfl_xor_sync(0xffffffffu, s0, 2);
    s1 += __shfl_xor_sync(0xffffffffu, s1, 1);
    s1 += __shfl_xor_sync(0xffffffffu, s1, 2);
    float inv0 = 1.f / s0, inv1 = 1.f / s1;

    // ---- repack weights as A fragments (C m16n16 == A m16k16 layout) ----
    uint32_t wa[2][4];
#pragma unroll
    for (int ks = 0; ks < 2; ks++) {
        const int n0t = ks * 2, n1t = ks * 2 + 1;
        wa[ks][0] = packh2(s[n0t][0] * inv0, s[n0t][1] * inv0);
        wa[ks][1] = packh2(s[n0t][2] * inv1, s[n0t][3] * inv1);
        wa[ks][2] = packh2(s[n1t][0] * inv0, s[n1t][1] * inv0);
        wa[ks][3] = packh2(s[n1t][2] * inv1, s[n1t][3] * inv1);
    }

    asm volatile("cp.async.wait_group 0;" ::: "memory");   // hs ready
    __syncthreads();

    // ---- context MMA: out_h[16 x 256] = W[16x32] x HSw_half[32x256] ----
    float* obase = out + (((size_t)b * HH + h) * SS + i0) * DD + dhalf * 256;
#pragma unroll
    for (int dp = 0; dp < 4; dp++) {
        float acc[8][4];
#pragma unroll
        for (int ni = 0; ni < 8; ni++)
#pragma unroll
            for (int r = 0; r < 4; r++) acc[ni][r] = 0.f;

#pragma unroll
        for (int ks = 0; ks < 2; ks++) {
#pragma unroll
            for (int ni = 0; ni < 8; ni++) {
                uint32_t bf[2];
                int kr = ks * 16 + (lane & 15);
                int cu = dp * 8 + ni;
                ldm_x2t(bf[0], bf[1], Bb + kr * 512 + ((cu ^ (kr & 7)) << 4));
                mma16816(acc[ni], wa[ks], bf);
            }
        }

        float* o0 = obase + (size_t)er * DD + dp * 64;
        float* o1 = o0 + 8 * (size_t)DD;
#pragma unroll
        for (int ni = 0; ni < 8; ni++) {
            *(float2*)(o0 + ni * 8 + ec) = make_float2(acc[ni][0], acc[ni][1]);
            *(float2*)(o1 + ni * 8 + ec) = make_float2(acc[ni][2], acc[ni][3]);
        }
    }
}

// ---------------------------------------------------------------------------
extern "C" void kernel_launch(void* const* d_in, const int* in_sizes, int n_in,
                              void* d_out, int out_size) {
    const float* hs = (const float*)d_in[0];
    const float* Wq = (const float*)d_in[1];
    const float* Wk = (const float*)d_in[2];
    float* out = (float*)d_out;

    cudaFuncSetAttribute(gemm2, cudaFuncAttributeMaxDynamicSharedMemorySize, GEMM_SMEM);
    cudaFuncSetAttribute(ctxf, cudaFuncAttributeMaxDynamicSharedMemorySize, CTXF_SMEM);

    split_hs<<<2048, 256>>>(hs);
    split_w<<<dim3(16, 16, 2), dim3(32, 8)>>>(Wq, Wk);
    gemm2<<<dim3(32, 4, 2), 256, GEMM_SMEM>>>();
    ctxf<<<dim3(NBLK * 2, BB), 256, CTXF_SMEM>>>(out);
}